// round 2
// baseline (speedup 1.0000x reference)
#include <cuda_runtime.h>
#include <math.h>

#define Bb 2
#define Tt 2048
#define Cc 2048
#define Hh 16
#define Dd 128
#define NTOK (Bb*Tt)   // 4096

// Scratch (device globals: no runtime allocation allowed)
__device__ float g_q[(size_t)NTOK*Cc];
__device__ float g_k[(size_t)NTOK*Cc];
__device__ float g_v[(size_t)NTOK*Cc];
__device__ float g_ctx[(size_t)NTOK*Cc];

// ---------------------------------------------------------------------------
// SGEMM: Co[n,m] = sum_k A[n,k]*W[m,k] (+ bias[m])
// A: [N,K] row-major, W: [M,K] row-major (nn.Linear weight), Co: [N,M]
// BM=BN=128, BK=8, 256 threads, 8x8 per-thread tile.
// ---------------------------------------------------------------------------
template<bool BIAS>
__global__ void __launch_bounds__(256) gemm_nt(const float* __restrict__ A,
                                               const float* __restrict__ W,
                                               const float* __restrict__ bias,
                                               float* __restrict__ Co,
                                               int N, int M, int K)
{
    __shared__ float As[8][128];
    __shared__ float Ws[8][128];

    const int bm = blockIdx.y * 128;
    const int bn = blockIdx.x * 128;
    const int tid = threadIdx.x;
    const int lr = tid >> 1;           // 0..127 (tile row loaded by this thread)
    const int lk = (tid & 1) * 4;      // 0 or 4 (k sub-offset)
    const int tx = tid & 15;
    const int ty = tid >> 4;

    const float* Aptr = A + (size_t)(bm + lr) * K + lk;
    const float* Wptr = W + (size_t)(bn + lr) * K + lk;

    float bvals[8];
    if (BIAS) {
        #pragma unroll
        for (int j = 0; j < 8; j++) bvals[j] = bias[bn + tx*8 + j];
    }

    float acc[8][8];
    #pragma unroll
    for (int i = 0; i < 8; i++)
        #pragma unroll
        for (int j = 0; j < 8; j++) acc[i][j] = 0.f;

    for (int k0 = 0; k0 < K; k0 += 8) {
        float4 a4 = *(const float4*)(Aptr + k0);
        float4 w4 = *(const float4*)(Wptr + k0);
        As[lk+0][lr] = a4.x; As[lk+1][lr] = a4.y; As[lk+2][lr] = a4.z; As[lk+3][lr] = a4.w;
        Ws[lk+0][lr] = w4.x; Ws[lk+1][lr] = w4.y; Ws[lk+2][lr] = w4.z; Ws[lk+3][lr] = w4.w;
        __syncthreads();

        #pragma unroll
        for (int kk = 0; kk < 8; kk++) {
            float4 a0 = *(const float4*)&As[kk][ty*8];
            float4 a1 = *(const float4*)&As[kk][ty*8 + 4];
            float4 b0 = *(const float4*)&Ws[kk][tx*8];
            float4 b1 = *(const float4*)&Ws[kk][tx*8 + 4];
            float af[8] = {a0.x,a0.y,a0.z,a0.w,a1.x,a1.y,a1.z,a1.w};
            float wf[8] = {b0.x,b0.y,b0.z,b0.w,b1.x,b1.y,b1.z,b1.w};
            #pragma unroll
            for (int i = 0; i < 8; i++)
                #pragma unroll
                for (int j = 0; j < 8; j++)
                    acc[i][j] += af[i] * wf[j];
        }
        __syncthreads();
    }

    #pragma unroll
    for (int i = 0; i < 8; i++) {
        const int row = bm + ty*8 + i;
        float* cp = Co + (size_t)row * M + bn + tx*8;
        float4 r0, r1;
        r0.x = acc[i][0] + (BIAS ? bvals[0] : 0.f);
        r0.y = acc[i][1] + (BIAS ? bvals[1] : 0.f);
        r0.z = acc[i][2] + (BIAS ? bvals[2] : 0.f);
        r0.w = acc[i][3] + (BIAS ? bvals[3] : 0.f);
        r1.x = acc[i][4] + (BIAS ? bvals[4] : 0.f);
        r1.y = acc[i][5] + (BIAS ? bvals[5] : 0.f);
        r1.z = acc[i][6] + (BIAS ? bvals[6] : 0.f);
        r1.w = acc[i][7] + (BIAS ? bvals[7] : 0.f);
        *(float4*)cp       = r0;
        *(float4*)(cp + 4) = r1;
    }
}

// ---------------------------------------------------------------------------
// Flash-attention (fp32). One CTA = one (b, h, 64-query tile).
// Streams 64-key tiles with online softmax. 256 threads (16x16).
// smem: Qt[128][68], Kt[128][68] (d-major), Vs[64][132], Pt[64][68] (s-major)
// ---------------------------------------------------------------------------
#define QT_OFF 0
#define KT_OFF (128*68)
#define VS_OFF (2*128*68)
#define PT_OFF (2*128*68 + 64*132)
#define SMEM_FLOATS (2*128*68 + 64*132 + 64*68)
#define SMEM_BYTES  (SMEM_FLOATS * 4)

__device__ __forceinline__ float warp16_max(float v) {
    #pragma unroll
    for (int off = 1; off < 16; off <<= 1)
        v = fmaxf(v, __shfl_xor_sync(0xffffffffu, v, off));
    return v;
}
__device__ __forceinline__ float warp16_sum(float v) {
    #pragma unroll
    for (int off = 1; off < 16; off <<= 1)
        v += __shfl_xor_sync(0xffffffffu, v, off);
    return v;
}

__global__ void __launch_bounds__(256) attn_kernel(const int* __restrict__ pm)
{
    extern __shared__ float sm[];
    float* Qt = sm + QT_OFF;
    float* Kt = sm + KT_OFF;
    float* Vs = sm + VS_OFF;
    float* Pt = sm + PT_OFF;

    const int qb = blockIdx.x;   // query tile (0..31)
    const int h  = blockIdx.y;
    const int b  = blockIdx.z;
    const int tid  = threadIdx.x;
    const int lane = tid & 31;
    const int warp = tid >> 5;
    const int tx = tid & 15;
    const int ty = tid >> 4;

    const size_t head_off = (size_t)h * Dd;
    const float* Qg = g_q + (size_t)b * Tt * Cc + head_off;
    const float* Kg = g_k + (size_t)b * Tt * Cc + head_off;
    const float* Vg = g_v + (size_t)b * Tt * Cc + head_off;

    // Load Q tile transposed: Qt[d][row]
    {
        const int row_base = qb * 64;
        #pragma unroll
        for (int it = 0; it < 8; it++) {
            const int row = it*8 + warp;
            float4 v4 = *(const float4*)(Qg + (size_t)(row_base + row) * Cc + lane*4);
            const int d = lane * 4;
            Qt[(d+0)*68 + row] = v4.x;
            Qt[(d+1)*68 + row] = v4.y;
            Qt[(d+2)*68 + row] = v4.z;
            Qt[(d+3)*68 + row] = v4.w;
        }
    }

    const int qrow0 = qb*64 + ty*4;
    int pmq[4];
    #pragma unroll
    for (int i = 0; i < 4; i++) pmq[i] = pm[b*Tt + qrow0 + i];

    float accO[4][8];
    #pragma unroll
    for (int i = 0; i < 4; i++)
        #pragma unroll
        for (int j = 0; j < 8; j++) accO[i][j] = 0.f;

    float m_i[4], l_i[4];
    #pragma unroll
    for (int i = 0; i < 4; i++) { m_i[i] = -INFINITY; l_i[i] = 0.f; }

    const float scale = 0.08838834764831845f;  // 1/sqrt(128)

    for (int kb = 0; kb <= qb; kb++) {
        __syncthreads();  // previous iteration done with Kt/Vs/Pt
        // Load K tile transposed (Kt[d][row]) and V tile row-major (Vs[row][d])
        {
            const int krow_base = kb * 64;
            #pragma unroll
            for (int it = 0; it < 8; it++) {
                const int row = it*8 + warp;
                const size_t goff = (size_t)(krow_base + row) * Cc + lane*4;
                float4 kv = *(const float4*)(Kg + goff);
                const int d = lane * 4;
                Kt[(d+0)*68 + row] = kv.x;
                Kt[(d+1)*68 + row] = kv.y;
                Kt[(d+2)*68 + row] = kv.z;
                Kt[(d+3)*68 + row] = kv.w;
                float4 vv = *(const float4*)(Vg + goff);
                *(float4*)&Vs[row*132 + d] = vv;
            }
        }
        __syncthreads();

        // S = Q * K^T  (4x4 per thread)
        float acc[4][4];
        #pragma unroll
        for (int i = 0; i < 4; i++)
            #pragma unroll
            for (int j = 0; j < 4; j++) acc[i][j] = 0.f;

        #pragma unroll 8
        for (int kk = 0; kk < 128; kk++) {
            float4 a = *(const float4*)&Qt[kk*68 + ty*4];
            float4 k4 = *(const float4*)&Kt[kk*68 + tx*4];
            float af[4] = {a.x, a.y, a.z, a.w};
            float wf[4] = {k4.x, k4.y, k4.z, k4.w};
            #pragma unroll
            for (int i = 0; i < 4; i++)
                #pragma unroll
                for (int j = 0; j < 4; j++)
                    acc[i][j] += af[i] * wf[j];
        }

        // Online softmax update
        #pragma unroll
        for (int i = 0; i < 4; i++) {
            const int q = qrow0 + i;
            float mx = -INFINITY;
            #pragma unroll
            for (int j = 0; j < 4; j++) {
                float s = acc[i][j] * scale;
                if (pmq[i] == 0) s = -1e9f;                 // padding mask (query rows)
                const int scol = kb*64 + tx*4 + j;
                if (scol > q) s = -INFINITY;                // causal mask
                acc[i][j] = s;
                mx = fmaxf(mx, s);
            }
            mx = warp16_max(mx);
            const float mnew = fmaxf(m_i[i], mx);
            const float sf = __expf(m_i[i] - mnew);         // 0 when m_i == -inf
            m_i[i] = mnew;
            float rs = 0.f;
            #pragma unroll
            for (int j = 0; j < 4; j++) {
                const float p = __expf(acc[i][j] - mnew);
                rs += p;
                Pt[(tx*4 + j)*68 + ty*4 + i] = p;           // store transposed
            }
            rs = warp16_sum(rs);
            l_i[i] = l_i[i]*sf + rs;
            #pragma unroll
            for (int jj = 0; jj < 8; jj++) accO[i][jj] *= sf;
        }
        __syncthreads();

        // O += P * V   (4x8 per thread)
        #pragma unroll 4
        for (int s = 0; s < 64; s++) {
            float4 a  = *(const float4*)&Pt[s*68 + ty*4];
            float4 v0 = *(const float4*)&Vs[s*132 + tx*8];
            float4 v1 = *(const float4*)&Vs[s*132 + tx*8 + 4];
            float af[4] = {a.x, a.y, a.z, a.w};
            float vf[8] = {v0.x,v0.y,v0.z,v0.w,v1.x,v1.y,v1.z,v1.w};
            #pragma unroll
            for (int i = 0; i < 4; i++)
                #pragma unroll
                for (int j = 0; j < 8; j++)
                    accO[i][j] += af[i] * vf[j];
        }
    }

    // Write ctx[b, q, h*D + col] = O / l
    #pragma unroll
    for (int i = 0; i < 4; i++) {
        const float inv = 1.0f / l_i[i];
        float4 o0, o1;
        o0.x = accO[i][0]*inv; o0.y = accO[i][1]*inv;
        o0.z = accO[i][2]*inv; o0.w = accO[i][3]*inv;
        o1.x = accO[i][4]*inv; o1.y = accO[i][5]*inv;
        o1.z = accO[i][6]*inv; o1.w = accO[i][7]*inv;
        float* cp = g_ctx + (size_t)(b*Tt + qrow0 + i) * Cc + head_off + tx*8;
        *(float4*)cp       = o0;
        *(float4*)(cp + 4) = o1;
    }
}

// ---------------------------------------------------------------------------
extern "C" void kernel_launch(void* const* d_in, const int* in_sizes, int n_in,
                              void* d_out, int out_size)
{
    (void)in_sizes; (void)n_in; (void)out_size;
    const float* x  = (const float*)d_in[0];
    const int*   pm = (const int*)  d_in[1];
    const float* Wq = (const float*)d_in[2];
    const float* Wk = (const float*)d_in[3];
    const float* Wv = (const float*)d_in[4];
    const float* Wp = (const float*)d_in[5];
    const float* bp = (const float*)d_in[6];
    float* out = (float*)d_out;

    float *q, *k, *v, *ctx;
    cudaGetSymbolAddress((void**)&q,   g_q);
    cudaGetSymbolAddress((void**)&k,   g_k);
    cudaGetSymbolAddress((void**)&v,   g_v);
    cudaGetSymbolAddress((void**)&ctx, g_ctx);

    dim3 tb(256);
    dim3 gg(Cc/128, NTOK/128);  // (16, 32)

    gemm_nt<false><<<gg, tb>>>(x, Wq, nullptr, q, NTOK, Cc, Cc);
    gemm_nt<false><<<gg, tb>>>(x, Wk, nullptr, k, NTOK, Cc, Cc);
    gemm_nt<false><<<gg, tb>>>(x, Wv, nullptr, v, NTOK, Cc, Cc);

    cudaFuncSetAttribute(attn_kernel, cudaFuncAttributeMaxDynamicSharedMemorySize, SMEM_BYTES);
    attn_kernel<<<dim3(Tt/64, Hh, Bb), tb, SMEM_BYTES>>>(pm);

    gemm_nt<true><<<gg, tb>>>(ctx, Wp, bp, out, NTOK, Cc, Cc);
}

// round 4
// speedup vs baseline: 2.0029x; 2.0029x over previous
#include <cuda_runtime.h>
#include <cstdint>
#include <math.h>

#define Bb 2
#define Tt 2048
#define Cc 2048
#define Hh 16
#define Dd 128
#define NTOK (Bb*Tt)   // 4096

// Scratch (device globals: no runtime allocation allowed)
__device__ float g_q[(size_t)NTOK*Cc];
__device__ float g_k[(size_t)NTOK*Cc];
__device__ float g_v[(size_t)NTOK*Cc];
__device__ float g_ctx[(size_t)NTOK*Cc];
__device__ float g_xr[(size_t)NTOK*Cc];
__device__ float g_wq[(size_t)Cc*Cc];
__device__ float g_wk[(size_t)Cc*Cc];
__device__ float g_wv[(size_t)Cc*Cc];
__device__ float g_wp[(size_t)Cc*Cc];

// ===========================================================================
// helpers
// ===========================================================================
__device__ __forceinline__ uint32_t smem_u32(const void* p) {
    uint32_t a;
    asm("{ .reg .u64 t; cvta.to.shared.u64 t, %1; cvt.u32.u64 %0, t; }" : "=r"(a) : "l"(p));
    return a;
}
__device__ __forceinline__ void cp_async16(uint32_t dst, const void* src) {
    asm volatile("cp.async.cg.shared.global [%0], [%1], 16;" :: "r"(dst), "l"(src) : "memory");
}
__device__ __forceinline__ void cp_commit() {
    asm volatile("cp.async.commit_group;" ::: "memory");
}
__device__ __forceinline__ void cp_wait1() {
    asm volatile("cp.async.wait_group 1;" ::: "memory");
}
__device__ __forceinline__ float rtf32(float x) {
    uint32_t o;
    asm("cvt.rna.tf32.f32 %0, %1;" : "=r"(o) : "f"(x));
    return __uint_as_float(o);
}
// m16n8k8 TF32 MMA, fp32 accumulate. A row-major [16x8], B col-major (stored [n][k]).
__device__ __forceinline__ void mma_tf32(float* c, const uint32_t* a, const uint32_t* b) {
    asm volatile(
        "mma.sync.aligned.m16n8k8.row.col.f32.tf32.tf32.f32 "
        "{%0,%1,%2,%3}, {%4,%5,%6,%7}, {%8,%9}, {%0,%1,%2,%3};"
        : "+f"(c[0]), "+f"(c[1]), "+f"(c[2]), "+f"(c[3])
        : "r"(a[0]), "r"(a[1]), "r"(a[2]), "r"(a[3]), "r"(b[0]), "r"(b[1]));
}

// ===========================================================================
// Round-to-TF32 preprocessing (unbiased RN; mma.sync truncates RZ internally)
// ===========================================================================
__global__ void __launch_bounds__(256) round_tf32_k(const float4* __restrict__ src,
                                                    float4* __restrict__ dst, int n4) {
    int i = blockIdx.x * blockDim.x + threadIdx.x;
    if (i < n4) {
        float4 v = src[i];
        v.x = rtf32(v.x); v.y = rtf32(v.y); v.z = rtf32(v.z); v.w = rtf32(v.w);
        dst[i] = v;
    }
}

// ===========================================================================
// TF32 mma.sync GEMM: C[m,n] = sum_k A[m,k]*W[n,k] (+ bias[n])
// CTA 128x128, BK=32, 3-stage cp.async pipeline, 256 threads.
// Warp grid 2(m) x 4(n): warp tile 64x32 -> 4 m16-tiles x 4 n8-tiles.
// smem XOR-swizzled (chunk j ^ (row&7)): conflict-free frag LDS, no padding.
// ===========================================================================
#define G_BK     32
#define G_STAGES 3
#define G_TSZ    (128*G_BK)            // floats per tile per stage (4096)
#define G_SMEM   (G_STAGES * 2 * G_TSZ * 4)   // 98304 bytes
#define G_NSTEP  (Cc / G_BK)           // 64

template<bool BIAS>
__device__ __forceinline__ void gemm_body(const float* __restrict__ A,
                                          const float* __restrict__ W,
                                          const float* __restrict__ bias,
                                          float* __restrict__ C)
{
    extern __shared__ float sm[];
    float* As = sm;                      // [STAGES][128*32]
    float* Bs = sm + G_STAGES * G_TSZ;   // [STAGES][128*32]
    const uint32_t asb = smem_u32(As);
    const uint32_t bsb = smem_u32(Bs);

    const int tid  = threadIdx.x;
    const int lane = tid & 31;
    const int warp = tid >> 5;
    const int n0 = blockIdx.x * 128;
    const int m0 = blockIdx.y * 128;
    const int wm = (warp & 1) * 64;      // warp m-offset in tile
    const int wn = (warp >> 1) * 32;     // warp n-offset in tile

    // loader indices: 4 chunks each for A and B per stage
    const int lr = tid >> 1;             // row 0..127 (2 threads/row, 4 chunks each)
    const int lj0 = (tid & 1) * 4;       // chunk 0..3 or 4..7
    const float* Ag = A + (size_t)(m0 + lr) * Cc;
    const float* Wg = W + (size_t)(n0 + lr) * Cc;
    const uint32_t swr = (uint32_t)(lr & 7);

    // fragment addressing (element k in row r lives at float offset k ^ (4*(r&7)))
    const int fr = lane >> 2;            // 0..7
    const int fc = lane & 3;             // 0..3

    float acc[4][4][4];
    #pragma unroll
    for (int i = 0; i < 4; i++)
        #pragma unroll
        for (int j = 0; j < 4; j++)
            #pragma unroll
            for (int q = 0; q < 4; q++) acc[i][j][q] = 0.f;

    // ---- prologue: prefetch stages 0,1 ----
    #pragma unroll
    for (int s = 0; s < 2; s++) {
        const int kof = s * G_BK;
        const uint32_t sa = asb + s * G_TSZ * 4;
        const uint32_t sb = bsb + s * G_TSZ * 4;
        #pragma unroll
        for (int j = 0; j < 4; j++) {
            const uint32_t dof = (lr*32 + (((lj0+j) ^ swr) << 2)) * 4;
            cp_async16(sa + dof, Ag + kof + (lj0+j)*4);
            cp_async16(sb + dof, Wg + kof + (lj0+j)*4);
        }
        cp_commit();
    }

    // ---- main loop ----
    for (int s = 0; s < G_NSTEP; s++) {
        cp_wait1();
        __syncthreads();

        // issue stage s+2 (empty commit keeps group accounting uniform)
        if (s + 2 < G_NSTEP) {
            const int st = (s + 2) % G_STAGES;
            const int kof = (s + 2) * G_BK;
            const uint32_t sa = asb + st * G_TSZ * 4;
            const uint32_t sb = bsb + st * G_TSZ * 4;
            #pragma unroll
            for (int j = 0; j < 4; j++) {
                const uint32_t dof = (lr*32 + (((lj0+j) ^ swr) << 2)) * 4;
                cp_async16(sa + dof, Ag + kof + (lj0+j)*4);
                cp_async16(sb + dof, Wg + kof + (lj0+j)*4);
            }
        }
        cp_commit();

        // compute on stage s
        const float* A_s = As + (s % G_STAGES) * G_TSZ;
        const float* B_s = Bs + (s % G_STAGES) * G_TSZ;

        #pragma unroll
        for (int ks = 0; ks < 4; ks++) {
            const int kb = ks * 8;
            uint32_t bf[4][2];
            #pragma unroll
            for (int ni = 0; ni < 4; ni++) {
                const int n = wn + ni*8 + fr;
                const int xn = (n & 7) << 2;
                bf[ni][0] = __float_as_uint(B_s[n*32 + ((kb + fc)     ^ xn)]);
                bf[ni][1] = __float_as_uint(B_s[n*32 + ((kb + fc + 4) ^ xn)]);
            }
            #pragma unroll
            for (int mi = 0; mi < 4; mi++) {
                const int m  = wm + mi*16 + fr;
                const int m2 = m + 8;
                const int xm  = (m  & 7) << 2;
                const int xm2 = (m2 & 7) << 2;
                uint32_t af[4];
                af[0] = __float_as_uint(A_s[m *32 + ((kb + fc)     ^ xm )]);
                af[1] = __float_as_uint(A_s[m2*32 + ((kb + fc)     ^ xm2)]);
                af[2] = __float_as_uint(A_s[m *32 + ((kb + fc + 4) ^ xm )]);
                af[3] = __float_as_uint(A_s[m2*32 + ((kb + fc + 4) ^ xm2)]);
                #pragma unroll
                for (int ni = 0; ni < 4; ni++)
                    mma_tf32(acc[mi][ni], af, bf[ni]);
            }
        }
        __syncthreads();
    }

    // ---- epilogue ----
    #pragma unroll
    for (int mi = 0; mi < 4; mi++) {
        const int r0 = m0 + wm + mi*16 + fr;
        #pragma unroll
        for (int ni = 0; ni < 4; ni++) {
            const int col = n0 + wn + ni*8 + fc*2;
            float b0 = 0.f, b1 = 0.f;
            if (BIAS) { b0 = __ldg(bias + col); b1 = __ldg(bias + col + 1); }
            float2 v0 = make_float2(acc[mi][ni][0] + b0, acc[mi][ni][1] + b1);
            float2 v1 = make_float2(acc[mi][ni][2] + b0, acc[mi][ni][3] + b1);
            *(float2*)(C + (size_t)r0       * Cc + col) = v0;
            *(float2*)(C + (size_t)(r0 + 8) * Cc + col) = v1;
        }
    }
}

__global__ void __launch_bounds__(256, 2)
gemm_tc_bias(const float* __restrict__ A, const float* __restrict__ W,
             const float* __restrict__ bias, float* __restrict__ C) {
    gemm_body<true>(A, W, bias, C);
}

// QKV fused: blockIdx.z selects projection
__global__ void __launch_bounds__(256, 2)
gemm_tc_qkv(const float* __restrict__ A,
            const float* __restrict__ W0, const float* __restrict__ W1,
            const float* __restrict__ W2,
            float* __restrict__ C0, float* __restrict__ C1, float* __restrict__ C2) {
    const float* W = (blockIdx.z == 0) ? W0 : (blockIdx.z == 1) ? W1 : W2;
    float*       C = (blockIdx.z == 0) ? C0 : (blockIdx.z == 1) ? C1 : C2;
    gemm_body<false>(A, W, nullptr, C);
}

// ===========================================================================
// Flash-attention (fp32). One CTA = one (b, h, 64-query tile). 256 threads.
// Pt aliased onto Kt buffer (smem ~101KB => 2 CTAs/SM).
// ===========================================================================
#define QT_OFF 0
#define KT_OFF (128*68)
#define VS_OFF (2*128*68)
#define PT_OFF KT_OFF
#define SMEM_FLOATS (2*128*68 + 64*132)
#define SMEM_BYTES  (SMEM_FLOATS * 4)

__device__ __forceinline__ float warp16_max(float v) {
    #pragma unroll
    for (int off = 1; off < 16; off <<= 1)
        v = fmaxf(v, __shfl_xor_sync(0xffffffffu, v, off));
    return v;
}
__device__ __forceinline__ float warp16_sum(float v) {
    #pragma unroll
    for (int off = 1; off < 16; off <<= 1)
        v += __shfl_xor_sync(0xffffffffu, v, off);
    return v;
}

__global__ void __launch_bounds__(256) attn_kernel(const int* __restrict__ pm)
{
    extern __shared__ float sm[];
    float* Qt = sm + QT_OFF;
    float* Kt = sm + KT_OFF;
    float* Vs = sm + VS_OFF;
    float* Pt = sm + PT_OFF;   // aliased onto Kt

    const int qb = blockIdx.x;
    const int h  = blockIdx.y;
    const int b  = blockIdx.z;
    const int tid  = threadIdx.x;
    const int lane = tid & 31;
    const int warp = tid >> 5;
    const int tx = tid & 15;
    const int ty = tid >> 4;

    const size_t head_off = (size_t)h * Dd;
    const float* Qg = g_q + (size_t)b * Tt * Cc + head_off;
    const float* Kg = g_k + (size_t)b * Tt * Cc + head_off;
    const float* Vg = g_v + (size_t)b * Tt * Cc + head_off;

    {
        const int row_base = qb * 64;
        #pragma unroll
        for (int it = 0; it < 8; it++) {
            const int row = it*8 + warp;
            float4 v4 = *(const float4*)(Qg + (size_t)(row_base + row) * Cc + lane*4);
            const int d = lane * 4;
            Qt[(d+0)*68 + row] = v4.x;
            Qt[(d+1)*68 + row] = v4.y;
            Qt[(d+2)*68 + row] = v4.z;
            Qt[(d+3)*68 + row] = v4.w;
        }
    }

    const int qrow0 = qb*64 + ty*4;
    int pmq[4];
    #pragma unroll
    for (int i = 0; i < 4; i++) pmq[i] = pm[b*Tt + qrow0 + i];

    float accO[4][8];
    #pragma unroll
    for (int i = 0; i < 4; i++)
        #pragma unroll
        for (int j = 0; j < 8; j++) accO[i][j] = 0.f;

    float m_i[4], l_i[4];
    #pragma unroll
    for (int i = 0; i < 4; i++) { m_i[i] = -INFINITY; l_i[i] = 0.f; }

    const float scale = 0.08838834764831845f;

    for (int kb = 0; kb <= qb; kb++) {
        __syncthreads();
        {
            const int krow_base = kb * 64;
            #pragma unroll
            for (int it = 0; it < 8; it++) {
                const int row = it*8 + warp;
                const size_t goff = (size_t)(krow_base + row) * Cc + lane*4;
                float4 kv = *(const float4*)(Kg + goff);
                const int d = lane * 4;
                Kt[(d+0)*68 + row] = kv.x;
                Kt[(d+1)*68 + row] = kv.y;
                Kt[(d+2)*68 + row] = kv.z;
                Kt[(d+3)*68 + row] = kv.w;
                float4 vv = *(const float4*)(Vg + goff);
                *(float4*)&Vs[row*132 + d] = vv;
            }
        }
        __syncthreads();

        float acc[4][4];
        #pragma unroll
        for (int i = 0; i < 4; i++)
            #pragma unroll
            for (int j = 0; j < 4; j++) acc[i][j] = 0.f;

        #pragma unroll 8
        for (int kk = 0; kk < 128; kk++) {
            float4 a  = *(const float4*)&Qt[kk*68 + ty*4];
            float4 k4 = *(const float4*)&Kt[kk*68 + tx*4];
            float af[4] = {a.x, a.y, a.z, a.w};
            float wf[4] = {k4.x, k4.y, k4.z, k4.w};
            #pragma unroll
            for (int i = 0; i < 4; i++)
                #pragma unroll
                for (int j = 0; j < 4; j++)
                    acc[i][j] += af[i] * wf[j];
        }

        __syncthreads();   // Kt reads done before Pt (aliased) writes

        #pragma unroll
        for (int i = 0; i < 4; i++) {
            const int q = qrow0 + i;
            float mx = -INFINITY;
            #pragma unroll
            for (int j = 0; j < 4; j++) {
                float s = acc[i][j] * scale;
                if (pmq[i] == 0) s = -1e9f;
                const int scol = kb*64 + tx*4 + j;
                if (scol > q) s = -INFINITY;
                acc[i][j] = s;
                mx = fmaxf(mx, s);
            }
            mx = warp16_max(mx);
            const float mnew = fmaxf(m_i[i], mx);
            const float sf = __expf(m_i[i] - mnew);
            m_i[i] = mnew;
            float rs = 0.f;
            #pragma unroll
            for (int j = 0; j < 4; j++) {
                const float p = __expf(acc[i][j] - mnew);
                rs += p;
                Pt[(tx*4 + j)*68 + ty*4 + i] = p;
            }
            rs = warp16_sum(rs);
            l_i[i] = l_i[i]*sf + rs;
            #pragma unroll
            for (int jj = 0; jj < 8; jj++) accO[i][jj] *= sf;
        }
        __syncthreads();

        #pragma unroll 4
        for (int s = 0; s < 64; s++) {
            float4 a  = *(const float4*)&Pt[s*68 + ty*4];
            float4 v0 = *(const float4*)&Vs[s*132 + tx*8];
            float4 v1 = *(const float4*)&Vs[s*132 + tx*8 + 4];
            float af[4] = {a.x, a.y, a.z, a.w};
            float vf[8] = {v0.x,v0.y,v0.z,v0.w,v1.x,v1.y,v1.z,v1.w};
            #pragma unroll
            for (int i = 0; i < 4; i++)
                #pragma unroll
                for (int j = 0; j < 8; j++)
                    accO[i][j] += af[i] * vf[j];
        }
    }

    // ctx written pre-rounded to tf32 (RN) for the output projection MMA
    #pragma unroll
    for (int i = 0; i < 4; i++) {
        const float inv = 1.0f / l_i[i];
        float4 o0, o1;
        o0.x = rtf32(accO[i][0]*inv); o0.y = rtf32(accO[i][1]*inv);
        o0.z = rtf32(accO[i][2]*inv); o0.w = rtf32(accO[i][3]*inv);
        o1.x = rtf32(accO[i][4]*inv); o1.y = rtf32(accO[i][5]*inv);
        o1.z = rtf32(accO[i][6]*inv); o1.w = rtf32(accO[i][7]*inv);
        float* cp = g_ctx + (size_t)(b*Tt + qrow0 + i) * Cc + head_off + tx*8;
        *(float4*)cp       = o0;
        *(float4*)(cp + 4) = o1;
    }
}

// ===========================================================================
extern "C" void kernel_launch(void* const* d_in, const int* in_sizes, int n_in,
                              void* d_out, int out_size)
{
    (void)in_sizes; (void)n_in; (void)out_size;
    const float* x  = (const float*)d_in[0];
    const int*   pm = (const int*)  d_in[1];
    const float* Wq = (const float*)d_in[2];
    const float* Wk = (const float*)d_in[3];
    const float* Wv = (const float*)d_in[4];
    const float* Wp = (const float*)d_in[5];
    const float* bp = (const float*)d_in[6];
    float* out = (float*)d_out;

    float *q, *k, *v, *ctx, *xr, *wq, *wk, *wv, *wp;
    cudaGetSymbolAddress((void**)&q,   g_q);
    cudaGetSymbolAddress((void**)&k,   g_k);
    cudaGetSymbolAddress((void**)&v,   g_v);
    cudaGetSymbolAddress((void**)&ctx, g_ctx);
    cudaGetSymbolAddress((void**)&xr,  g_xr);
    cudaGetSymbolAddress((void**)&wq,  g_wq);
    cudaGetSymbolAddress((void**)&wk,  g_wk);
    cudaGetSymbolAddress((void**)&wv,  g_wv);
    cudaGetSymbolAddress((void**)&wp,  g_wp);

    // Pre-round MMA operands to tf32 (RN) — removes truncation bias
    const int n4x = NTOK*Cc/4, n4w = Cc*Cc/4;
    round_tf32_k<<<(n4x+255)/256, 256>>>((const float4*)x,  (float4*)xr, n4x);
    round_tf32_k<<<(n4w+255)/256, 256>>>((const float4*)Wq, (float4*)wq, n4w);
    round_tf32_k<<<(n4w+255)/256, 256>>>((const float4*)Wk, (float4*)wk, n4w);
    round_tf32_k<<<(n4w+255)/256, 256>>>((const float4*)Wv, (float4*)wv, n4w);
    round_tf32_k<<<(n4w+255)/256, 256>>>((const float4*)Wp, (float4*)wp, n4w);

    cudaFuncSetAttribute(gemm_tc_qkv,  cudaFuncAttributeMaxDynamicSharedMemorySize, G_SMEM);
    cudaFuncSetAttribute(gemm_tc_bias, cudaFuncAttributeMaxDynamicSharedMemorySize, G_SMEM);
    cudaFuncSetAttribute(attn_kernel,  cudaFuncAttributeMaxDynamicSharedMemorySize, SMEM_BYTES);

    // QKV projections (fused launch), tensor-pipe tf32 mma.sync
    gemm_tc_qkv<<<dim3(Cc/128, NTOK/128, 3), 256, G_SMEM>>>(xr, wq, wk, wv, q, k, v);

    // attention
    attn_kernel<<<dim3(Tt/64, Hh, Bb), 256, SMEM_BYTES>>>(pm);

    // output projection + bias
    gemm_tc_bias<<<dim3(Cc/128, NTOK/128), 256, G_SMEM>>>(ctx, wp, bp, out);
}

// round 5
// speedup vs baseline: 2.7160x; 1.3560x over previous
#include <cuda_runtime.h>
#include <cstdint>
#include <math.h>

#define Bb 2
#define Tt 2048
#define Cc 2048
#define Hh 16
#define Dd 128
#define NTOK (Bb*Tt)   // 4096

// Scratch (device globals: no runtime allocation allowed)
__device__ float g_q[(size_t)NTOK*Cc];
__device__ float g_k[(size_t)NTOK*Cc];
__device__ float g_v[(size_t)NTOK*Cc];
__device__ float g_ctx[(size_t)NTOK*Cc];
__device__ float g_xr[(size_t)NTOK*Cc];
__device__ float g_wq[(size_t)Cc*Cc];
__device__ float g_wk[(size_t)Cc*Cc];
__device__ float g_wv[(size_t)Cc*Cc];
__device__ float g_wp[(size_t)Cc*Cc];

// ===========================================================================
// helpers
// ===========================================================================
__device__ __forceinline__ uint32_t smem_u32(const void* p) {
    uint32_t a;
    asm("{ .reg .u64 t; cvta.to.shared.u64 t, %1; cvt.u32.u64 %0, t; }" : "=r"(a) : "l"(p));
    return a;
}
__device__ __forceinline__ void cp_async16(uint32_t dst, const void* src) {
    asm volatile("cp.async.cg.shared.global [%0], [%1], 16;" :: "r"(dst), "l"(src) : "memory");
}
__device__ __forceinline__ void cp_commit() {
    asm volatile("cp.async.commit_group;" ::: "memory");
}
__device__ __forceinline__ void cp_wait1() {
    asm volatile("cp.async.wait_group 1;" ::: "memory");
}
__device__ __forceinline__ void cp_wait0() {
    asm volatile("cp.async.wait_group 0;" ::: "memory");
}
__device__ __forceinline__ float rtf32(float x) {
    uint32_t o;
    asm("cvt.rna.tf32.f32 %0, %1;" : "=r"(o) : "f"(x));
    return __uint_as_float(o);
}
__device__ __forceinline__ uint32_t rtf32u(float x) {
    uint32_t o;
    asm("cvt.rna.tf32.f32 %0, %1;" : "=r"(o) : "f"(x));
    return o;
}
// m16n8k8 TF32 MMA, fp32 accumulate. A row-major [16x8], B col-major (stored [n][k]).
__device__ __forceinline__ void mma_tf32(float* c, const uint32_t* a, const uint32_t* b) {
    asm volatile(
        "mma.sync.aligned.m16n8k8.row.col.f32.tf32.tf32.f32 "
        "{%0,%1,%2,%3}, {%4,%5,%6,%7}, {%8,%9}, {%0,%1,%2,%3};"
        : "+f"(c[0]), "+f"(c[1]), "+f"(c[2]), "+f"(c[3])
        : "r"(a[0]), "r"(a[1]), "r"(a[2]), "r"(a[3]), "r"(b[0]), "r"(b[1]));
}

// ===========================================================================
// Fused round-to-TF32 preprocessing (z selects buffer)
// ===========================================================================
__global__ void __launch_bounds__(256) round_tf32_all(
    const float4* __restrict__ x,  float4* __restrict__ xr,
    const float4* __restrict__ w0, float4* __restrict__ r0,
    const float4* __restrict__ w1, float4* __restrict__ r1,
    const float4* __restrict__ w2, float4* __restrict__ r2,
    const float4* __restrict__ w3, float4* __restrict__ r3)
{
    const int z = blockIdx.z;
    const float4* src; float4* dst; int n4;
    if      (z == 0) { src = x;  dst = xr; n4 = NTOK*Cc/4; }
    else if (z == 1) { src = w0; dst = r0; n4 = Cc*Cc/4; }
    else if (z == 2) { src = w1; dst = r1; n4 = Cc*Cc/4; }
    else if (z == 3) { src = w2; dst = r2; n4 = Cc*Cc/4; }
    else             { src = w3; dst = r3; n4 = Cc*Cc/4; }
    int i = blockIdx.x * blockDim.x + threadIdx.x;
    if (i < n4) {
        float4 v = src[i];
        v.x = rtf32(v.x); v.y = rtf32(v.y); v.z = rtf32(v.z); v.w = rtf32(v.w);
        dst[i] = v;
    }
}

// ===========================================================================
// TF32 mma.sync GEMM: C[m,n] = sum_k A[m,k]*W[n,k] (+ bias[n])
// CTA 128x256, 8 warps, warp tile 64x64 (2m x 4n), BK=32, 3-stage cp.async.
// smem XOR-swizzled. 144KB smem -> 1 CTA/SM.
// ===========================================================================
#define G_BK     32
#define G_STAGES 3
#define G_ATSZ   (128*G_BK)            // 4096 floats
#define G_BTSZ   (256*G_BK)            // 8192 floats
#define G_SMEM   (G_STAGES*(G_ATSZ+G_BTSZ)*4)   // 147456 bytes
#define G_NSTEP  (Cc / G_BK)           // 64

template<bool BIAS, bool ROUND>
__device__ __forceinline__ void gemm_body(const float* __restrict__ A,
                                          const float* __restrict__ W,
                                          const float* __restrict__ bias,
                                          float* __restrict__ C)
{
    extern __shared__ float sm[];
    float* As = sm;                          // [3][128*32]
    float* Bs = sm + G_STAGES * G_ATSZ;      // [3][256*32]
    const uint32_t asb = smem_u32(As);
    const uint32_t bsb = smem_u32(Bs);

    const int tid  = threadIdx.x;
    const int lane = tid & 31;
    const int warp = tid >> 5;
    const int n0 = blockIdx.x * 256;
    const int m0 = blockIdx.y * 128;
    const int wm = (warp & 1) * 64;
    const int wn = (warp >> 1) * 64;
    const int fr = lane >> 2;
    const int fc = lane & 3;

    // loaders: A 128 rows x 8 chunks (2 thr/row, 4 chunks each); B 256 rows x 8 chunks
    const int lrA = tid >> 1;
    const int ljA = (tid & 1) * 4;
    const float* Ag = A + (size_t)(m0 + lrA) * Cc;
    const float* Wg = W + (size_t)(n0 + tid) * Cc;
    const uint32_t swA = (uint32_t)(lrA & 7);
    const uint32_t swB = (uint32_t)(tid & 7);

    float acc[4][8][4];
    #pragma unroll
    for (int i = 0; i < 4; i++)
        #pragma unroll
        for (int j = 0; j < 8; j++)
            #pragma unroll
            for (int q = 0; q < 4; q++) acc[i][j][q] = 0.f;

    #define G_LOAD(s, st) do {                                                  \
        const uint32_t sa = asb + (st) * (G_ATSZ*4);                             \
        const uint32_t sb = bsb + (st) * (G_BTSZ*4);                             \
        const int kof = (s) * G_BK;                                              \
        _Pragma("unroll")                                                        \
        for (int j = 0; j < 4; j++) {                                            \
            const int ch = ljA + j;                                              \
            cp_async16(sa + (lrA*32 + (((uint32_t)ch ^ swA) << 2)) * 4,          \
                       Ag + kof + ch*4);                                         \
        }                                                                        \
        _Pragma("unroll")                                                        \
        for (int j = 0; j < 8; j++) {                                            \
            cp_async16(sb + (tid*32 + (((uint32_t)j ^ swB) << 2)) * 4,           \
                       Wg + kof + j*4);                                          \
        }                                                                        \
    } while (0)

    G_LOAD(0, 0); cp_commit();
    G_LOAD(1, 1); cp_commit();

    for (int s = 0; s < G_NSTEP; s++) {
        cp_wait1();
        __syncthreads();
        if (s + 2 < G_NSTEP) { G_LOAD(s + 2, (s + 2) % G_STAGES); }
        cp_commit();

        const float* A_s = As + (s % G_STAGES) * G_ATSZ;
        const float* B_s = Bs + (s % G_STAGES) * G_BTSZ;

        #pragma unroll
        for (int ks = 0; ks < 4; ks++) {
            const int kb = ks * 8;
            uint32_t bf[8][2];
            #pragma unroll
            for (int ni = 0; ni < 8; ni++) {
                const int n = wn + ni*8 + fr;
                const int xn = (n & 7) << 2;
                bf[ni][0] = __float_as_uint(B_s[n*32 + ((kb + fc)     ^ xn)]);
                bf[ni][1] = __float_as_uint(B_s[n*32 + ((kb + fc + 4) ^ xn)]);
            }
            #pragma unroll
            for (int mi = 0; mi < 4; mi++) {
                const int m  = wm + mi*16 + fr;
                const int m2 = m + 8;
                const int xm  = (m  & 7) << 2;
                const int xm2 = (m2 & 7) << 2;
                uint32_t af[4];
                af[0] = __float_as_uint(A_s[m *32 + ((kb + fc)     ^ xm )]);
                af[1] = __float_as_uint(A_s[m2*32 + ((kb + fc)     ^ xm2)]);
                af[2] = __float_as_uint(A_s[m *32 + ((kb + fc + 4) ^ xm )]);
                af[3] = __float_as_uint(A_s[m2*32 + ((kb + fc + 4) ^ xm2)]);
                #pragma unroll
                for (int ni = 0; ni < 8; ni++)
                    mma_tf32(acc[mi][ni], af, bf[ni]);
            }
        }
        __syncthreads();
    }
    #undef G_LOAD

    // epilogue
    #pragma unroll
    for (int mi = 0; mi < 4; mi++) {
        const int r0 = m0 + wm + mi*16 + fr;
        #pragma unroll
        for (int ni = 0; ni < 8; ni++) {
            const int col = n0 + wn + ni*8 + fc*2;
            float v0 = acc[mi][ni][0], v1 = acc[mi][ni][1];
            float v2 = acc[mi][ni][2], v3 = acc[mi][ni][3];
            if (BIAS) {
                const float b0 = __ldg(bias + col), b1 = __ldg(bias + col + 1);
                v0 += b0; v1 += b1; v2 += b0; v3 += b1;
            }
            if (ROUND) { v0 = rtf32(v0); v1 = rtf32(v1); v2 = rtf32(v2); v3 = rtf32(v3); }
            *(float2*)(C + (size_t)r0       * Cc + col) = make_float2(v0, v1);
            *(float2*)(C + (size_t)(r0 + 8) * Cc + col) = make_float2(v2, v3);
        }
    }
}

__global__ void __launch_bounds__(256, 1)
gemm_tc_bias(const float* __restrict__ A, const float* __restrict__ W,
             const float* __restrict__ bias, float* __restrict__ C) {
    gemm_body<true, false>(A, W, bias, C);
}

// QKV fused: blockIdx.z selects projection; outputs RN-rounded to tf32
__global__ void __launch_bounds__(256, 1)
gemm_tc_qkv(const float* __restrict__ A,
            const float* __restrict__ W0, const float* __restrict__ W1,
            const float* __restrict__ W2,
            float* __restrict__ C0, float* __restrict__ C1, float* __restrict__ C2) {
    const float* W = (blockIdx.z == 0) ? W0 : (blockIdx.z == 1) ? W1 : W2;
    float*       C = (blockIdx.z == 0) ? C0 : (blockIdx.z == 1) ? C1 : C2;
    gemm_body<false, true>(A, W, nullptr, C);
}

// ===========================================================================
// Flash-attention, tf32 mma.sync. CTA = 128 threads (4 warps), one
// (b, h, 64-query tile). Q fragments register-resident. Ps aliases Qs.
// smem 102400B -> 2 CTAs/SM.
// ===========================================================================
#define A_QS  0
#define A_KS  (64*132)
#define A_VT  (2*64*132)
#define A_SMEMF (2*64*132 + 128*68)
#define A_SMEMB (A_SMEMF*4)   // 102400

__global__ void __launch_bounds__(128) attn_mma(const int* __restrict__ pm)
{
    extern __shared__ float sm[];
    float* Qs = sm + A_QS;   // [64][132]; later reused as Ps [64][68]
    float* Ks = sm + A_KS;   // [64][132]
    float* Vt = sm + A_VT;   // [128][68]
    float* Ps = Qs;
    const uint32_t qsb = smem_u32(Qs);
    const uint32_t ksb = smem_u32(Ks);

    const int qb = blockIdx.x;
    const int h  = blockIdx.y;
    const int b  = blockIdx.z;
    const int tid  = threadIdx.x;
    const int lane = tid & 31;
    const int warp = tid >> 5;
    const int fr = lane >> 2;
    const int fc = lane & 3;

    const size_t hoff = (size_t)h * Dd;
    const float* Qg = g_q + (size_t)b * Tt * Cc + hoff;
    const float* Kg = g_k + (size_t)b * Tt * Cc + hoff;
    const float* Vg = g_v + (size_t)b * Tt * Cc + hoff;
    const int q0 = qb * 64;

    // ---- load Q tile [64][128] into Qs (stride 132) ----
    #pragma unroll
    for (int i = 0; i < 16; i++) {
        const int id = i*128 + tid;
        const int r = id >> 5, ch = id & 31;
        cp_async16(qsb + (r*132 + ch*4)*4, Qg + (size_t)(q0 + r)*Cc + ch*4);
    }
    cp_commit(); cp_wait0();
    __syncthreads();

    // ---- Q fragments (scaled, RN-rounded), register-resident ----
    const float scale = 0.08838834764831845f;   // 1/sqrt(128)
    uint32_t qf[16][4];
    {
        const int m = warp*16 + fr;
        #pragma unroll
        for (int kb = 0; kb < 16; kb++) {
            const int k0 = kb*8;
            qf[kb][0] = rtf32u(Qs[m     *132 + k0 + fc    ] * scale);
            qf[kb][1] = rtf32u(Qs[(m+8) *132 + k0 + fc    ] * scale);
            qf[kb][2] = rtf32u(Qs[m     *132 + k0 + fc + 4] * scale);
            qf[kb][3] = rtf32u(Qs[(m+8) *132 + k0 + fc + 4] * scale);
        }
    }

    const int rowA = q0 + warp*16 + fr;
    const int rowB = rowA + 8;
    const int pmA = pm[b*Tt + rowA];
    const int pmB = pm[b*Tt + rowB];

    float o[16][4];
    #pragma unroll
    for (int i = 0; i < 16; i++)
        #pragma unroll
        for (int j = 0; j < 4; j++) o[i][j] = 0.f;
    float mA = -INFINITY, mB = -INFINITY, lA = 0.f, lB = 0.f;

    for (int kt = 0; kt <= qb; kt++) {
        __syncthreads();   // prev tile done reading Ks/Vt/Ps (and Q frags built)

        // K tile -> Ks (cp.async), V tile -> Vt transposed (ld+sts)
        #pragma unroll
        for (int i = 0; i < 16; i++) {
            const int id = i*128 + tid;
            const int r = id >> 5, ch = id & 31;
            cp_async16(ksb + (r*132 + ch*4)*4, Kg + (size_t)(kt*64 + r)*Cc + ch*4);
        }
        cp_commit();
        #pragma unroll
        for (int i = 0; i < 16; i++) {
            const int id = i*128 + tid;
            const int s = id >> 5, d0 = (id & 31) * 4;
            float4 v4 = *(const float4*)(Vg + (size_t)(kt*64 + s)*Cc + d0);
            Vt[(d0+0)*68 + s] = v4.x;
            Vt[(d0+1)*68 + s] = v4.y;
            Vt[(d0+2)*68 + s] = v4.z;
            Vt[(d0+3)*68 + s] = v4.w;
        }
        cp_wait0();
        __syncthreads();

        // ---- S = Q K^T ----
        float sa[8][4];
        #pragma unroll
        for (int ni = 0; ni < 8; ni++)
            #pragma unroll
            for (int j = 0; j < 4; j++) sa[ni][j] = 0.f;

        #pragma unroll
        for (int kb = 0; kb < 16; kb++) {
            const int k0 = kb*8;
            #pragma unroll
            for (int ni = 0; ni < 8; ni++) {
                uint32_t bf[2];
                bf[0] = __float_as_uint(Ks[(ni*8 + fr)*132 + k0 + fc    ]);
                bf[1] = __float_as_uint(Ks[(ni*8 + fr)*132 + k0 + fc + 4]);
                mma_tf32(sa[ni], qf[kb], bf);
            }
        }

        // ---- mask + online softmax ----
        float mxA = -INFINITY, mxB = -INFINITY;
        #pragma unroll
        for (int ni = 0; ni < 8; ni++) {
            const int c0 = kt*64 + ni*8 + 2*fc;
            float s0 = sa[ni][0], s1 = sa[ni][1], s2 = sa[ni][2], s3 = sa[ni][3];
            if (pmA == 0) { s0 = -1e9f; s1 = -1e9f; }
            if (pmB == 0) { s2 = -1e9f; s3 = -1e9f; }
            if (kt == qb) {
                if (c0     > rowA) s0 = -INFINITY;
                if (c0 + 1 > rowA) s1 = -INFINITY;
                if (c0     > rowB) s2 = -INFINITY;
                if (c0 + 1 > rowB) s3 = -INFINITY;
            }
            sa[ni][0] = s0; sa[ni][1] = s1; sa[ni][2] = s2; sa[ni][3] = s3;
            mxA = fmaxf(mxA, fmaxf(s0, s1));
            mxB = fmaxf(mxB, fmaxf(s2, s3));
        }
        mxA = fmaxf(mxA, __shfl_xor_sync(0xffffffffu, mxA, 1));
        mxA = fmaxf(mxA, __shfl_xor_sync(0xffffffffu, mxA, 2));
        mxB = fmaxf(mxB, __shfl_xor_sync(0xffffffffu, mxB, 1));
        mxB = fmaxf(mxB, __shfl_xor_sync(0xffffffffu, mxB, 2));

        const float mnA = fmaxf(mA, mxA), mnB = fmaxf(mB, mxB);
        const float sfA = __expf(mA - mnA), sfB = __expf(mB - mnB);
        mA = mnA; mB = mnB;

        float suA = 0.f, suB = 0.f;
        #pragma unroll
        for (int ni = 0; ni < 8; ni++) {
            float p0 = rtf32(__expf(sa[ni][0] - mA));
            float p1 = rtf32(__expf(sa[ni][1] - mA));
            float p2 = rtf32(__expf(sa[ni][2] - mB));
            float p3 = rtf32(__expf(sa[ni][3] - mB));
            suA += p0 + p1; suB += p2 + p3;
            const int sc = ni*8 + 2*fc;
            *(float2*)&Ps[(warp*16 + fr    )*68 + sc] = make_float2(p0, p1);
            *(float2*)&Ps[(warp*16 + fr + 8)*68 + sc] = make_float2(p2, p3);
        }
        suA += __shfl_xor_sync(0xffffffffu, suA, 1);
        suA += __shfl_xor_sync(0xffffffffu, suA, 2);
        suB += __shfl_xor_sync(0xffffffffu, suB, 1);
        suB += __shfl_xor_sync(0xffffffffu, suB, 2);
        lA = lA*sfA + suA;
        lB = lB*sfB + suB;
        #pragma unroll
        for (int ni = 0; ni < 16; ni++) {
            o[ni][0] *= sfA; o[ni][1] *= sfA;
            o[ni][2] *= sfB; o[ni][3] *= sfB;
        }
        __syncthreads();   // Ps complete before PV reads

        // ---- O += P V ----
        #pragma unroll
        for (int kb = 0; kb < 8; kb++) {
            const int k0 = kb*8;
            uint32_t af[4];
            af[0] = __float_as_uint(Ps[(warp*16 + fr    )*68 + k0 + fc    ]);
            af[1] = __float_as_uint(Ps[(warp*16 + fr + 8)*68 + k0 + fc    ]);
            af[2] = __float_as_uint(Ps[(warp*16 + fr    )*68 + k0 + fc + 4]);
            af[3] = __float_as_uint(Ps[(warp*16 + fr + 8)*68 + k0 + fc + 4]);
            #pragma unroll
            for (int ni = 0; ni < 16; ni++) {
                uint32_t bf[2];
                bf[0] = __float_as_uint(Vt[(ni*8 + fr)*68 + k0 + fc    ]);
                bf[1] = __float_as_uint(Vt[(ni*8 + fr)*68 + k0 + fc + 4]);
                mma_tf32(o[ni], af, bf);
            }
        }
    }

    // ---- epilogue: ctx = O / l, RN-rounded to tf32 for the proj GEMM ----
    const float iA = 1.f / lA, iB = 1.f / lB;
    float* cpA = g_ctx + (size_t)(b*Tt + rowA)*Cc + hoff;
    float* cpB = g_ctx + (size_t)(b*Tt + rowB)*Cc + hoff;
    #pragma unroll
    for (int ni = 0; ni < 16; ni++) {
        const int d0 = ni*8 + 2*fc;
        *(float2*)(cpA + d0) = make_float2(rtf32(o[ni][0]*iA), rtf32(o[ni][1]*iA));
        *(float2*)(cpB + d0) = make_float2(rtf32(o[ni][2]*iB), rtf32(o[ni][3]*iB));
    }
}

// ===========================================================================
extern "C" void kernel_launch(void* const* d_in, const int* in_sizes, int n_in,
                              void* d_out, int out_size)
{
    (void)in_sizes; (void)n_in; (void)out_size;
    const float* x  = (const float*)d_in[0];
    const int*   pm = (const int*)  d_in[1];
    const float* Wq = (const float*)d_in[2];
    const float* Wk = (const float*)d_in[3];
    const float* Wv = (const float*)d_in[4];
    const float* Wp = (const float*)d_in[5];
    const float* bp = (const float*)d_in[6];
    float* out = (float*)d_out;

    float *q, *k, *v, *ctx, *xr, *wq, *wk, *wv, *wp;
    cudaGetSymbolAddress((void**)&q,   g_q);
    cudaGetSymbolAddress((void**)&k,   g_k);
    cudaGetSymbolAddress((void**)&v,   g_v);
    cudaGetSymbolAddress((void**)&ctx, g_ctx);
    cudaGetSymbolAddress((void**)&xr,  g_xr);
    cudaGetSymbolAddress((void**)&wq,  g_wq);
    cudaGetSymbolAddress((void**)&wk,  g_wk);
    cudaGetSymbolAddress((void**)&wv,  g_wv);
    cudaGetSymbolAddress((void**)&wp,  g_wp);

    // Pre-round all MMA source operands to tf32 (RN), one fused launch
    const int nb = (NTOK*Cc/4 + 255) / 256;   // largest buffer (x)
    round_tf32_all<<<dim3(nb, 1, 5), 256>>>(
        (const float4*)x,  (float4*)xr,
        (const float4*)Wq, (float4*)wq,
        (const float4*)Wk, (float4*)wk,
        (const float4*)Wv, (float4*)wv,
        (const float4*)Wp, (float4*)wp);

    cudaFuncSetAttribute(gemm_tc_qkv,  cudaFuncAttributeMaxDynamicSharedMemorySize, G_SMEM);
    cudaFuncSetAttribute(gemm_tc_bias, cudaFuncAttributeMaxDynamicSharedMemorySize, G_SMEM);
    cudaFuncSetAttribute(attn_mma,     cudaFuncAttributeMaxDynamicSharedMemorySize, A_SMEMB);

    // QKV projections (fused launch), outputs RN-rounded tf32
    gemm_tc_qkv<<<dim3(Cc/256, NTOK/128, 3), 256, G_SMEM>>>(xr, wq, wk, wv, q, k, v);

    // attention (tensor-core flash)
    attn_mma<<<dim3(Tt/64, Hh, Bb), 128, A_SMEMB>>>(pm);

    // output projection + bias
    gemm_tc_bias<<<dim3(Cc/256, NTOK/128), 256, G_SMEM>>>(ctx, wp, bp, out);
}